// round 1
// baseline (speedup 1.0000x reference)
#include <cuda_runtime.h>
#include <cuda_bf16.h>
#include <math.h>

#define BATCH 32
#define NGT 20
#define HWA 10647
#define NUM_CLASSES 80
#define FP16_EPS_F 0.0009765625
#define BCE_EPS 1e-6f

// accumulator layout:
// [0..31]    per-batch cls sum
// [32..63]   per-batch txty sum
// [64..95]   per-batch twth sum
// [96..127]  per-batch positive count
// [128] conf_pos_sum  [129] conf_neg_sum  [130] neg_count
#define ACC_N 131

__device__ unsigned long long g_event[BATCH * HWA];
__device__ double g_acc[ACC_N];

__constant__ float c_anc[9][2] = {
    {0.024f, 0.031f}, {0.038f, 0.072f}, {0.079f, 0.055f},
    {0.072f, 0.147f}, {0.149f, 0.108f}, {0.142f, 0.286f},
    {0.279f, 0.216f}, {0.375f, 0.476f}, {0.897f, 0.784f}};

__device__ __forceinline__ int grid_of(int j) { return (j == 0) ? 52 : ((j == 1) ? 26 : 13); }
__device__ __forceinline__ int off_of(int j)  { return (j == 0) ? 0  : ((j == 1) ? 2704 : 3380); }

__global__ void zero_kernel() {
    int t = blockIdx.x * blockDim.x + threadIdx.x;
    if (t < BATCH * HWA) g_event[t] = 0ull;
    if (t < ACC_N) g_acc[t] = 0.0;
}

// One block per batch item. Replicates the sequential scan's final state via
// priority atomicMax. priority = 2*(3*p + j) + is_pos, p = i*NGT + k.
__global__ void scatter_kernel(const float* __restrict__ gb) {
    int b = blockIdx.x;
    int tid = threadIdx.x;
    __shared__ float scx[NGT], scy[NGT];
    __shared__ int sa[NGT];

    if (tid < NGT) {
        const float* p = gb + (b * NGT + tid) * 4;
        float l = p[0], tp = p[1], r = p[2], bo = p[3];
        float cx = (l + r) * 0.5f, cy = (tp + bo) * 0.5f;
        float w = r - l, h = bo - tp;
        scx[tid] = cx; scy[tid] = cy;
        float area = w * h;
        float best = -1.0f; int bi = 0;
        #pragma unroll
        for (int a = 0; a < 9; a++) {
            float aw = c_anc[a][0], ah = c_anc[a][1];
            float inter = fminf(w, aw) * fminf(h, ah);
            float uni = area + aw * ah - inter;
            float iou = inter / uni;
            if (iou > best) { best = iou; bi = a; }  // first-max, like jnp.argmax
        }
        sa[tid] = bi;
    }
    __syncthreads();

    unsigned long long* ev = g_event + (size_t)b * HWA;

    // Negative (ignore) events: for fixed (i,j) all k hit the same 3 rows;
    // only k = NGT-1 (max priority among them) can win the atomicMax.
    for (int e = tid; e < NGT * 3; e += blockDim.x) {
        int i = e / 3, j = e % 3;
        int grid = grid_of(j), off = off_of(j);
        int col = (int)(scx[i] * (float)grid);
        int row = (int)(scy[i] * (float)grid);
        int idx = (off + row * grid + col) * 3;
        int p = i * NGT + (NGT - 1);
        unsigned long long pr = 2ull * (unsigned long long)(3 * p + j);  // even = neg
        unsigned long long val = (1ull << 63) | (pr << 16);
        atomicMax(&ev[idx + 0], val);
        atomicMax(&ev[idx + 1], val);
        atomicMax(&ev[idx + 2], val);
    }

    // Positive events: for each (i,k), anchor a = sa[k]; written at scale j = a/3
    // within the j-loop of step p = i*NGT+k, AFTER that step's neg write (pr|1).
    for (int e = tid; e < NGT * NGT; e += blockDim.x) {
        int i = e / NGT, k = e % NGT;
        int a = sa[k];
        int j = a / 3;
        int grid = grid_of(j), off = off_of(j);
        int col = (int)(scx[i] * (float)grid);
        int row = (int)(scy[i] * (float)grid);
        int idx = (off + row * grid + col) * 3 + (a % 3);
        unsigned long long pr = 2ull * (unsigned long long)(3 * e + j) + 1ull;  // odd = pos
        unsigned long long val = (1ull << 63) | (pr << 16) |
                                 ((unsigned long long)i << 8) | (unsigned long long)a;
        atomicMax(&ev[idx], val);
    }
}

__device__ __forceinline__ float sigf(float x) { return 1.0f / (1.0f + expf(-x)); }
__device__ __forceinline__ float bcef(float p, float g) {
    p = fminf(fmaxf(p, BCE_EPS), 1.0f - BCE_EPS);
    return -(g * logf(p) + (1.0f - g) * logf(1.0f - p));
}

__global__ void reduce_kernel(const float* __restrict__ pconf,
                              const float* __restrict__ pcls,
                              const float* __restrict__ ptxywh,
                              const float* __restrict__ gb,
                              const int* __restrict__ glab) {
    int t = blockIdx.x * blockDim.x + threadIdx.x;
    float neg_sum = 0.0f;
    int neg_cnt = 0;

    if (t < BATCH * HWA) {
        int b = t / HWA;
        unsigned long long v = g_event[t];
        float s = sigf(pconf[t]);
        if (v == 0ull) {
            // gconf == 0 : negative
            neg_sum = s * s;
            neg_cnt = 1;
        } else if ((v >> 16) & 1ull) {
            // last col-0 write was a positive full-row write: conf = 1
            int i = (int)((v >> 8) & 0xFFull);
            int a = (int)(v & 0xFFull);

            float d = s - 1.0f;
            atomicAdd(&g_acc[128], (double)(d * d));
            atomicAdd(&g_acc[96 + b], 1.0);

            const float* bx = gb + (b * NGT + i) * 4;
            float l = bx[0], tp = bx[1], r = bx[2], bo = bx[3];
            float cx = (l + r) * 0.5f, cy = (tp + bo) * 0.5f;
            float w = r - l, h = bo - tp;
            int j = a / 3;
            int grid = grid_of(j);
            float gridf = (float)grid;
            int col = (int)(cx * gridf);
            int row = (int)(cy * gridf);
            float tx = (cx - (float)col / gridf) * gridf;
            float ty = (cy - (float)row / gridf) * gridf;
            float twx = logf(w / c_anc[a][0]);
            float twy = logf(h / c_anc[a][1]);
            float wt = 2.0f - w * h;
            int lbl = glab[b * NGT + i] - 1;

            // 80-class BCE vs one-hot
            const float* pc = pcls + (size_t)t * NUM_CLASSES;
            float cls = 0.0f;
            #pragma unroll 8
            for (int c = 0; c < NUM_CLASSES; c++) {
                float p = sigf(pc[c]);
                p = fminf(fmaxf(p, BCE_EPS), 1.0f - BCE_EPS);
                cls += (c == lbl) ? -logf(p) : -logf(1.0f - p);
            }
            atomicAdd(&g_acc[b], (double)cls);

            const float* pt = ptxywh + (size_t)t * 4;
            float bce_xy = bcef(sigf(pt[0]), tx) + bcef(sigf(pt[1]), ty);
            atomicAdd(&g_acc[32 + b], (double)(bce_xy * wt));
            float d2 = pt[2] - twx, d3 = pt[3] - twy;
            atomicAdd(&g_acc[64 + b], (double)((d2 * d2 + d3 * d3) * wt));
        }
        // else: winner was a neg event -> conf = -1 -> ignored everywhere
    }

    // block-reduce the dominant negative contributions
    __shared__ float ssum[256];
    __shared__ int scnt[256];
    ssum[threadIdx.x] = neg_sum;
    scnt[threadIdx.x] = neg_cnt;
    __syncthreads();
    for (int st = 128; st > 0; st >>= 1) {
        if (threadIdx.x < st) {
            ssum[threadIdx.x] += ssum[threadIdx.x + st];
            scnt[threadIdx.x] += scnt[threadIdx.x + st];
        }
        __syncthreads();
    }
    if (threadIdx.x == 0) {
        atomicAdd(&g_acc[129], (double)ssum[0]);
        atomicAdd(&g_acc[130], (double)scnt[0]);
    }
}

__global__ void final_kernel(float* __restrict__ out) {
    if (blockIdx.x == 0 && threadIdx.x == 0) {
        double pos_total = 0.0, cls = 0.0, txty = 0.0, twth = 0.0;
        for (int b = 0; b < BATCH; b++) {
            double np = g_acc[96 + b];
            pos_total += np;
            double npc = (np < FP16_EPS_F) ? FP16_EPS_F : np;
            cls  += g_acc[b] / npc;
            txty += g_acc[32 + b] / npc;
            twth += g_acc[64 + b] / npc;
        }
        double l_conf_pos = g_acc[128] / pos_total * 30.0;
        double l_conf_neg = g_acc[129] / g_acc[130] * 30.0;
        double loss = l_conf_pos + l_conf_neg +
                      cls / BATCH + txty / BATCH + twth / BATCH;
        out[0] = (float)loss;
    }
}

extern "C" void kernel_launch(void* const* d_in, const int* in_sizes, int n_in,
                              void* d_out, int out_size) {
    const float* pconf  = (const float*)d_in[0];
    const float* pcls   = (const float*)d_in[1];
    const float* ptxywh = (const float*)d_in[2];
    const float* gb     = (const float*)d_in[3];
    const int*   glab   = (const int*)d_in[4];
    float* out = (float*)d_out;

    const int total = BATCH * HWA;
    const int threads = 256;
    const int blocks = (total + threads - 1) / threads;

    zero_kernel<<<blocks, threads>>>();
    scatter_kernel<<<BATCH, 128>>>(gb);
    reduce_kernel<<<blocks, threads>>>(pconf, pcls, ptxywh, gb, glab);
    final_kernel<<<1, 32>>>(out);
}

// round 2
// speedup vs baseline: 1.9512x; 1.9512x over previous
#include <cuda_runtime.h>
#include <cuda_bf16.h>
#include <math.h>

#define BATCH 32
#define NGT 20
#define HWA 10647
#define NUM_CLASSES 80
#define FP16_EPS_F 0.0009765625
#define BCE_EPS 1e-6f

// accumulator layout:
// [0..31]    per-batch cls sum
// [32..63]   per-batch txty sum
// [64..95]   per-batch twth sum
// [96..127]  per-batch positive count
// [128] conf_pos_sum  [129] conf_neg_sum  [130] neg_count
#define ACC_N 131

#define TOTAL (BATCH * HWA)           // 340704
#define TOTAL4 (TOTAL / 4)            // 85176 (exact)
#define RED_THREADS 256
#define RED_BLOCKS ((TOTAL + RED_THREADS - 1) / RED_THREADS)  // 1331.x -> 1332

__device__ unsigned int g_event[TOTAL];
__device__ double g_acc[ACC_N];
__device__ unsigned int g_done;

__constant__ float c_anc[9][2] = {
    {0.024f, 0.031f}, {0.038f, 0.072f}, {0.079f, 0.055f},
    {0.072f, 0.147f}, {0.149f, 0.108f}, {0.142f, 0.286f},
    {0.279f, 0.216f}, {0.375f, 0.476f}, {0.897f, 0.784f}};

__device__ __forceinline__ int grid_of(int j) { return (j == 0) ? 52 : ((j == 1) ? 26 : 13); }
__device__ __forceinline__ int off_of(int j)  { return (j == 0) ? 0  : ((j == 1) ? 2704 : 3380); }

__global__ void zero_kernel() {
    int t = blockIdx.x * blockDim.x + threadIdx.x;
    if (t < TOTAL4) {
        ((uint4*)g_event)[t] = make_uint4(0u, 0u, 0u, 0u);
    }
    if (blockIdx.x == 0) {
        if (t < ACC_N) g_acc[t] = 0.0;
        if (t == ACC_N) g_done = 0u;
    }
}

// One block per batch item. Replicates the sequential scan's final state via
// priority atomicMax. priority = 2*(3*p + j) + is_pos, p = i*NGT + k.
// 32-bit event: [pr:12 | i:5 | a:4] ; is_pos = bit 9 (pr's LSB).
__global__ void scatter_kernel(const float* __restrict__ gb) {
    int b = blockIdx.x;
    int tid = threadIdx.x;
    __shared__ float scx[NGT], scy[NGT];
    __shared__ int sa[NGT];

    if (tid < NGT) {
        const float* p = gb + (b * NGT + tid) * 4;
        float l = p[0], tp = p[1], r = p[2], bo = p[3];
        float cx = (l + r) * 0.5f, cy = (tp + bo) * 0.5f;
        float w = r - l, h = bo - tp;
        scx[tid] = cx; scy[tid] = cy;
        float area = w * h;
        float best = -1.0f; int bi = 0;
        #pragma unroll
        for (int a = 0; a < 9; a++) {
            float aw = c_anc[a][0], ah = c_anc[a][1];
            float inter = fminf(w, aw) * fminf(h, ah);
            float uni = area + aw * ah - inter;
            float iou = inter / uni;
            if (iou > best) { best = iou; bi = a; }  // first-max, like jnp.argmax
        }
        sa[tid] = bi;
    }
    __syncthreads();

    unsigned int* ev = g_event + (size_t)b * HWA;

    // Negative (ignore) events: for fixed (i,j) all k hit the same 3 rows;
    // only k = NGT-1 (max priority among them) can win the atomicMax.
    for (int e = tid; e < NGT * 3; e += blockDim.x) {
        int i = e / 3, j = e % 3;
        int grid = grid_of(j), off = off_of(j);
        int col = (int)(scx[i] * (float)grid);
        int row = (int)(scy[i] * (float)grid);
        int idx = (off + row * grid + col) * 3;
        int p = i * NGT + (NGT - 1);
        unsigned int pr = 2u * (unsigned int)(3 * p + j);  // even = neg
        unsigned int val = pr << 9;
        atomicMax(&ev[idx + 0], val);
        atomicMax(&ev[idx + 1], val);
        atomicMax(&ev[idx + 2], val);
    }

    // Positive events: for each (i,k), anchor a = sa[k]; written at scale j = a/3
    // within the j-loop of step p = i*NGT+k, AFTER that step's neg write (pr|1).
    for (int e = tid; e < NGT * NGT; e += blockDim.x) {
        int i = e / NGT, k = e % NGT;
        int a = sa[k];
        int j = a / 3;
        int grid = grid_of(j), off = off_of(j);
        int col = (int)(scx[i] * (float)grid);
        int row = (int)(scy[i] * (float)grid);
        int idx = (off + row * grid + col) * 3 + (a % 3);
        unsigned int pr = 2u * (unsigned int)(3 * e + j) + 1u;  // odd = pos
        unsigned int val = (pr << 9) | ((unsigned int)i << 4) | (unsigned int)a;
        atomicMax(&ev[idx], val);
    }
}

__device__ __forceinline__ float sigf(float x) { return 1.0f / (1.0f + expf(-x)); }
__device__ __forceinline__ float bcef(float p, float g) {
    p = fminf(fmaxf(p, BCE_EPS), 1.0f - BCE_EPS);
    return -(g * logf(p) + (1.0f - g) * logf(1.0f - p));
}

__device__ __forceinline__ double warp_sum_d(double v) {
    #pragma unroll
    for (int s = 16; s > 0; s >>= 1)
        v += __shfl_xor_sync(0xFFFFFFFFu, v, s);
    return v;
}

__global__ void reduce_kernel(const float* __restrict__ pconf,
                              const float* __restrict__ pcls,
                              const float* __restrict__ ptxywh,
                              const float* __restrict__ gb,
                              const int* __restrict__ glab,
                              float* __restrict__ out) {
    int t = blockIdx.x * blockDim.x + threadIdx.x;
    float neg_sum = 0.0f;
    int neg_cnt = 0;

    if (t < TOTAL) {
        int b = t / HWA;
        unsigned int v = g_event[t];
        float s = sigf(pconf[t]);
        if (v == 0u) {
            // gconf == 0 : negative
            neg_sum = s * s;
            neg_cnt = 1;
        } else if ((v >> 9) & 1u) {
            // last col-0 write was a positive full-row write: conf = 1
            int i = (int)((v >> 4) & 0x1Fu);
            int a = (int)(v & 0xFu);

            float d = s - 1.0f;
            atomicAdd(&g_acc[128], (double)(d * d));
            atomicAdd(&g_acc[96 + b], 1.0);

            const float* bx = gb + (b * NGT + i) * 4;
            float l = bx[0], tp = bx[1], r = bx[2], bo = bx[3];
            float cx = (l + r) * 0.5f, cy = (tp + bo) * 0.5f;
            float w = r - l, h = bo - tp;
            int j = a / 3;
            int grid = grid_of(j);
            float gridf = (float)grid;
            int col = (int)(cx * gridf);
            int row = (int)(cy * gridf);
            float tx = (cx - (float)col / gridf) * gridf;
            float ty = (cy - (float)row / gridf) * gridf;
            float twx = logf(w / c_anc[a][0]);
            float twy = logf(h / c_anc[a][1]);
            float wt = 2.0f - w * h;
            int lbl = glab[b * NGT + i] - 1;

            // 80-class BCE vs one-hot
            const float* pc = pcls + (size_t)t * NUM_CLASSES;
            float cls = 0.0f;
            #pragma unroll 8
            for (int c = 0; c < NUM_CLASSES; c++) {
                float p = sigf(pc[c]);
                p = fminf(fmaxf(p, BCE_EPS), 1.0f - BCE_EPS);
                cls += (c == lbl) ? -logf(p) : -logf(1.0f - p);
            }
            atomicAdd(&g_acc[b], (double)cls);

            const float* pt = ptxywh + (size_t)t * 4;
            float bce_xy = bcef(sigf(pt[0]), tx) + bcef(sigf(pt[1]), ty);
            atomicAdd(&g_acc[32 + b], (double)(bce_xy * wt));
            float d2 = pt[2] - twx, d3 = pt[3] - twy;
            atomicAdd(&g_acc[64 + b], (double)((d2 * d2 + d3 * d3) * wt));
        }
        // else: winner was a neg event -> conf = -1 -> ignored everywhere
    }

    // block-reduce the negative contributions (warp shuffles, then smem)
    __shared__ float wsum[RED_THREADS / 32];
    __shared__ int wcnt[RED_THREADS / 32];
    #pragma unroll
    for (int st = 16; st > 0; st >>= 1) {
        neg_sum += __shfl_xor_sync(0xFFFFFFFFu, neg_sum, st);
        neg_cnt += __shfl_xor_sync(0xFFFFFFFFu, neg_cnt, st);
    }
    int lane = threadIdx.x & 31, warp = threadIdx.x >> 5;
    if (lane == 0) { wsum[warp] = neg_sum; wcnt[warp] = neg_cnt; }
    __syncthreads();
    if (threadIdx.x == 0) {
        float fs = 0.0f; int fc = 0;
        #pragma unroll
        for (int wv = 0; wv < RED_THREADS / 32; wv++) { fs += wsum[wv]; fc += wcnt[wv]; }
        atomicAdd(&g_acc[129], (double)fs);
        atomicAdd(&g_acc[130], (double)fc);
    }
    __syncthreads();

    // ---- last-block-done: final combine, parallel over 32 lanes ----
    __shared__ unsigned int s_is_last;
    if (threadIdx.x == 0) {
        __threadfence();
        unsigned int prev = atomicAdd(&g_done, 1u);
        s_is_last = (prev == (unsigned int)(gridDim.x - 1)) ? 1u : 0u;
    }
    __syncthreads();
    if (s_is_last && threadIdx.x < 32) {
        int b = threadIdx.x;
        volatile double* acc = g_acc;
        double np  = acc[96 + b];
        double npc = (np < (double)FP16_EPS_F) ? (double)FP16_EPS_F : np;
        double cls  = acc[b]      / npc;
        double txty = acc[32 + b] / npc;
        double twth = acc[64 + b] / npc;
        double per_batch = (cls + txty + twth) / (double)BATCH;
        double sum_pb = warp_sum_d(per_batch);
        double sum_np = warp_sum_d(np);
        if (b == 0) {
            double l_conf_pos = acc[128] / sum_np * 30.0;
            double l_conf_neg = acc[129] / acc[130] * 30.0;
            out[0] = (float)(l_conf_pos + l_conf_neg + sum_pb);
        }
    }
}

extern "C" void kernel_launch(void* const* d_in, const int* in_sizes, int n_in,
                              void* d_out, int out_size) {
    const float* pconf  = (const float*)d_in[0];
    const float* pcls   = (const float*)d_in[1];
    const float* ptxywh = (const float*)d_in[2];
    const float* gb     = (const float*)d_in[3];
    const int*   glab   = (const int*)d_in[4];
    float* out = (float*)d_out;

    const int zthreads = 256;
    const int zblocks = (TOTAL4 + zthreads - 1) / zthreads;

    zero_kernel<<<zblocks, zthreads>>>();
    scatter_kernel<<<BATCH, 128>>>(gb);
    reduce_kernel<<<RED_BLOCKS, RED_THREADS>>>(pconf, pcls, ptxywh, gb, glab, out);
}